// round 10
// baseline (speedup 1.0000x reference)
#include <cuda_runtime.h>

#define NUM_G 4096
#define D4    32          // 128 floats = 32 float4 per row
#define DHID  128
#define TPB   512
#define RG    16          // row groups in pass 1 (TPB / 32)
#define EPSV  1e-5f
#define GRID  304         // 2 persistent blocks per SM (152 SMs on GB300)

__device__ int g_seg_off[NUM_G + 1];

// Scan-based offsets: thread i compares batch[i-1] vs batch[i] (sorted) and
// fills g_seg_off[g] = lower_bound(g) for every boundary it owns.
// Runtime dtype detection: if batch is int64 (LE), odd 32-bit words near the end
// are high words of values < 4096 -> all zero. If int32, tail values ~4095.
__global__ void offsets_kernel(const int* __restrict__ b32, int n)
{
    int i = blockIdx.x * blockDim.x + threadIdx.x;
    if (i > n) return;
    int probe = b32[n - 1] | b32[n - 3] | b32[n - 5] | b32[n - 7];
    int sh = (probe == 0) ? 1 : 0;   // 1 => int64, read low words at stride 2
    int prev = (i > 0) ? b32[(long long)(i - 1) << sh] : -1;
    int cur  = (i < n) ? b32[(long long)i << sh]       : NUM_G;
    for (int g = prev + 1; g <= cur; ++g)
        g_seg_off[g] = i;
}

__device__ __forceinline__ void acc(float4& s, float4& q, const float4 v)
{
    s.x += v.x; s.y += v.y; s.z += v.z; s.w += v.w;
    q.x += v.x * v.x; q.y += v.y * v.y;
    q.z += v.z * v.z; q.w += v.w * v.w;
}

__global__ __launch_bounds__(TPB, 2) void graphnorm_kernel(
    const float4* __restrict__ x4,
    const float*  __restrict__ weight,
    const float*  __restrict__ bias,
    float4*       __restrict__ out4)
{
    __shared__ float4 red_s[RG][D4];
    __shared__ float4 red_q[RG][D4];
    __shared__ float4 sc_s[D4];
    __shared__ float4 sh_s[D4];

    const int tid = threadIdx.x;
    const int c4  = tid & (D4 - 1);   // float4 column
    const int rg  = tid >> 5;         // row group 0..15

    // Persistent loop over graphs. No extra barriers needed: sc_s/sh_s
    // (read in pass 2) are distinct from red_s/red_q (written next pass 1),
    // and the reduce that overwrites sc_s sits behind a full barrier.
    for (int g = blockIdx.x; g < NUM_G; g += GRID) {

        const int start = g_seg_off[g];
        const int end   = g_seg_off[g + 1];
        const int cnt   = end - start;

        // ---- Pass 1: per-column sum / sumsq (unroll x4: 4 independent
        //      LDG.128 per warp in flight) ----
        float4 s = make_float4(0.f, 0.f, 0.f, 0.f);
        float4 q = make_float4(0.f, 0.f, 0.f, 0.f);
        int r = start + rg;
        for (; r + 3 * RG < end; r += 4 * RG) {
            float4 v0 = x4[(r         ) * D4 + c4];
            float4 v1 = x4[(r +     RG) * D4 + c4];
            float4 v2 = x4[(r + 2 * RG) * D4 + c4];
            float4 v3 = x4[(r + 3 * RG) * D4 + c4];
            acc(s, q, v0);
            acc(s, q, v1);
            acc(s, q, v2);
            acc(s, q, v3);
        }
        for (; r < end; r += RG) {
            float4 v = x4[r * D4 + c4];
            acc(s, q, v);
        }
        red_s[rg][c4] = s;
        red_q[rg][c4] = q;
        __syncthreads();

        // ---- Flat parallel reduction + fold into scale/shift.
        //      128 threads, one scalar column each: 16 conflict-free LDS
        //      per sum, fully pipelined. ----
        if (tid < DHID) {
            const float* ps = reinterpret_cast<const float*>(red_s);
            const float* pq = reinterpret_cast<const float*>(red_q);
            float S = 0.f, Q = 0.f;
            #pragma unroll
            for (int k = 0; k < RG; ++k) {
                S += ps[k * DHID + tid];
                Q += pq[k * DHID + tid];
            }
            float w = weight[tid];
            float b = bias[tid];
            float sc, sh;
            if (cnt > 1) {
                float inv_n = 1.0f / (float)cnt;
                float m = S * inv_n;
                float v = Q * inv_n - m * m;
                sc = w * rsqrtf(v + EPSV);
                sh = b - m * sc;
            } else {
                // cnt <= 1: reference leaves mean=0, var=1
                sc = w * rsqrtf(1.0f + EPSV);
                sh = b;
            }
            reinterpret_cast<float*>(sc_s)[tid] = sc;
            reinterpret_cast<float*>(sh_s)[tid] = sh;
        }
        __syncthreads();

        // ---- Pass 2: normalize (unroll x2, hoisted sc/sh). x re-read hits
        //      L2; streaming stores keep the output from evicting x. ----
        const float4 sc = sc_s[c4];
        const float4 sh = sh_s[c4];
        const int jend = end * D4;
        int j = start * D4 + tid;
        for (; j + TPB < jend; j += 2 * TPB) {
            float4 v0 = x4[j];
            float4 v1 = x4[j + TPB];
            float4 o0, o1;
            o0.x = v0.x * sc.x + sh.x; o0.y = v0.y * sc.y + sh.y;
            o0.z = v0.z * sc.z + sh.z; o0.w = v0.w * sc.w + sh.w;
            o1.x = v1.x * sc.x + sh.x; o1.y = v1.y * sc.y + sh.y;
            o1.z = v1.z * sc.z + sh.z; o1.w = v1.w * sc.w + sh.w;
            __stcs(&out4[j      ], o0);
            __stcs(&out4[j + TPB], o1);
        }
        if (j < jend) {
            float4 v = x4[j];
            float4 o;
            o.x = v.x * sc.x + sh.x;
            o.y = v.y * sc.y + sh.y;
            o.z = v.z * sc.z + sh.z;
            o.w = v.w * sc.w + sh.w;
            __stcs(&out4[j], o);
        }
    }
}

extern "C" void kernel_launch(void* const* d_in, const int* in_sizes, int n_in,
                              void* d_out, int out_size)
{
    const float* x      = (const float*)d_in[0];
    const int*   batch  = (const int*)d_in[1];   // int32 or int64; detected on device
    const float* weight = (const float*)d_in[2];
    const float* bias   = (const float*)d_in[3];
    float*       out    = (float*)d_out;

    int n = in_sizes[1];  // number of nodes

    offsets_kernel<<<(n + 1 + 255) / 256, 256>>>(batch, n);
    graphnorm_kernel<<<GRID, TPB>>>(
        reinterpret_cast<const float4*>(x), weight, bias,
        reinterpret_cast<float4*>(out));
}

// round 11
// speedup vs baseline: 1.0540x; 1.0540x over previous
#include <cuda_runtime.h>

#define NUM_G 4096
#define D4    32          // 128 floats = 32 float4 per row
#define DHID  128
#define TPB   512
#define RG    16          // row groups in pass 1 (TPB / 32)
#define EPSV  1e-5f

__device__ int g_seg_off[NUM_G + 1];

// Scan-based offsets: thread i compares batch[i-1] vs batch[i] (sorted) and
// fills g_seg_off[g] = lower_bound(g) for every boundary it owns.
// Runtime dtype detection: if batch is int64 (LE), odd 32-bit words near the end
// are high words of values < 4096 -> all zero. If int32, tail values ~4095.
__global__ void offsets_kernel(const int* __restrict__ b32, int n)
{
    int i = blockIdx.x * blockDim.x + threadIdx.x;
    if (i > n) return;
    int probe = b32[n - 1] | b32[n - 3] | b32[n - 5] | b32[n - 7];
    int sh = (probe == 0) ? 1 : 0;   // 1 => int64, read low words at stride 2
    int prev = (i > 0) ? b32[(long long)(i - 1) << sh] : -1;
    int cur  = (i < n) ? b32[(long long)i << sh]       : NUM_G;
    for (int g = prev + 1; g <= cur; ++g)
        g_seg_off[g] = i;
}

__device__ __forceinline__ void acc(float4& s, float4& q, const float4 v)
{
    s.x += v.x; s.y += v.y; s.z += v.z; s.w += v.w;
    q.x += v.x * v.x; q.y += v.y * v.y;
    q.z += v.z * v.z; q.w += v.w * v.w;
}

__global__ __launch_bounds__(TPB, 2) void graphnorm_kernel(
    const float4* __restrict__ x4,
    const float*  __restrict__ weight,
    const float*  __restrict__ bias,
    float4*       __restrict__ out4)
{
    __shared__ float4 red_s[RG][D4];
    __shared__ float4 red_q[RG][D4];
    __shared__ float4 sc_s[D4];
    __shared__ float4 sh_s[D4];

    const int g   = blockIdx.x;
    const int tid = threadIdx.x;
    const int c4  = tid & (D4 - 1);   // float4 column
    const int rg  = tid >> 5;         // row group 0..15

    const int start = g_seg_off[g];
    const int end   = g_seg_off[g + 1];
    const int cnt   = end - start;

    // ---- Pass 1: per-column sum / sumsq (unroll x4: 4 independent
    //      LDG.128 per warp in flight) ----
    float4 s = make_float4(0.f, 0.f, 0.f, 0.f);
    float4 q = make_float4(0.f, 0.f, 0.f, 0.f);
    int r = start + rg;
    for (; r + 3 * RG < end; r += 4 * RG) {
        float4 v0 = x4[(r         ) * D4 + c4];
        float4 v1 = x4[(r +     RG) * D4 + c4];
        float4 v2 = x4[(r + 2 * RG) * D4 + c4];
        float4 v3 = x4[(r + 3 * RG) * D4 + c4];
        acc(s, q, v0);
        acc(s, q, v1);
        acc(s, q, v2);
        acc(s, q, v3);
    }
    for (; r < end; r += RG) {
        float4 v = x4[r * D4 + c4];
        acc(s, q, v);
    }
    red_s[rg][c4] = s;
    red_q[rg][c4] = q;
    __syncthreads();

    // ---- Flat parallel reduction + fold into scale/shift.
    //      128 threads, one scalar column each: 16 conflict-free LDS per
    //      sum, fully pipelined. 2 barriers total. ----
    if (tid < DHID) {
        const float* ps = reinterpret_cast<const float*>(red_s);
        const float* pq = reinterpret_cast<const float*>(red_q);
        float S = 0.f, Q = 0.f;
        #pragma unroll
        for (int k = 0; k < RG; ++k) {
            S += ps[k * DHID + tid];
            Q += pq[k * DHID + tid];
        }
        float w = weight[tid];
        float b = bias[tid];
        float sc, sh;
        if (cnt > 1) {
            float inv_n = 1.0f / (float)cnt;
            float m = S * inv_n;
            float v = Q * inv_n - m * m;
            sc = w * rsqrtf(v + EPSV);
            sh = b - m * sc;
        } else {
            // cnt <= 1: reference leaves mean=0, var=1
            sc = w * rsqrtf(1.0f + EPSV);
            sh = b;
        }
        reinterpret_cast<float*>(sc_s)[tid] = sc;
        reinterpret_cast<float*>(sh_s)[tid] = sh;
    }
    __syncthreads();

    // ---- Pass 2: normalize (unroll x2, hoisted sc/sh). x re-read is the
    //      LAST use of each line: __ldcs (evict-first) frees L2 capacity
    //      immediately for other blocks' pass-1 streams. Streaming stores
    //      keep the output from evicting x segments. ----
    const float4 sc = sc_s[c4];
    const float4 sh = sh_s[c4];
    const int jend = end * D4;
    int j = start * D4 + tid;
    for (; j + TPB < jend; j += 2 * TPB) {
        float4 v0 = __ldcs(&x4[j]);
        float4 v1 = __ldcs(&x4[j + TPB]);
        float4 o0, o1;
        o0.x = v0.x * sc.x + sh.x; o0.y = v0.y * sc.y + sh.y;
        o0.z = v0.z * sc.z + sh.z; o0.w = v0.w * sc.w + sh.w;
        o1.x = v1.x * sc.x + sh.x; o1.y = v1.y * sc.y + sh.y;
        o1.z = v1.z * sc.z + sh.z; o1.w = v1.w * sc.w + sh.w;
        __stcs(&out4[j      ], o0);
        __stcs(&out4[j + TPB], o1);
    }
    if (j < jend) {
        float4 v = __ldcs(&x4[j]);
        float4 o;
        o.x = v.x * sc.x + sh.x;
        o.y = v.y * sc.y + sh.y;
        o.z = v.z * sc.z + sh.z;
        o.w = v.w * sc.w + sh.w;
        __stcs(&out4[j], o);
    }
}

extern "C" void kernel_launch(void* const* d_in, const int* in_sizes, int n_in,
                              void* d_out, int out_size)
{
    const float* x      = (const float*)d_in[0];
    const int*   batch  = (const int*)d_in[1];   // int32 or int64; detected on device
    const float* weight = (const float*)d_in[2];
    const float* bias   = (const float*)d_in[3];
    float*       out    = (float*)d_out;

    int n = in_sizes[1];  // number of nodes

    offsets_kernel<<<(n + 1 + 255) / 256, 256>>>(batch, n);
    graphnorm_kernel<<<NUM_G, TPB>>>(
        reinterpret_cast<const float4*>(x), weight, bias,
        reinterpret_cast<float4*>(out));
}

// round 12
// speedup vs baseline: 1.0730x; 1.0180x over previous
#include <cuda_runtime.h>

#define NUM_G 4096
#define D4    32          // 128 floats = 32 float4 per row
#define DHID  128
#define TPB   512
#define RG    16          // row groups in pass 1 (TPB / 32)
#define EPSV  1e-5f

__device__ int g_seg_off[NUM_G + 1];

// Vectorized scan-based offsets: each thread owns 4 consecutive positions
// i0..i0+3 of the virtual sequence val(-1)=-1, val(i)=batch[i] (i<n),
// val(n)=NUM_G, and writes g_seg_off[g]=i for every boundary it owns.
// Runtime dtype detection: if batch is int64 (LE), odd 32-bit words near the
// end are high words of values < 4096 -> all zero. If int32, tail ~4095.
__global__ void offsets_kernel(const int* __restrict__ b32, int n)
{
    int t  = blockIdx.x * blockDim.x + threadIdx.x;
    int i0 = t * 4;
    if (i0 > n) return;
    int probe = b32[n - 1] | b32[n - 3] | b32[n - 5] | b32[n - 7];
    int sh = (probe == 0) ? 1 : 0;   // 1 => int64, element i at word (i << 1)

    int prev = (i0 > 0) ? b32[(long long)(i0 - 1) << sh] : -1;

    int v[4];
    if (sh == 0) {
        if (i0 + 3 < n) {
            int4 a = *reinterpret_cast<const int4*>(b32 + i0);   // 16B aligned
            v[0] = a.x; v[1] = a.y; v[2] = a.z; v[3] = a.w;
        } else {
            #pragma unroll
            for (int j = 0; j < 4; ++j)
                v[j] = (i0 + j < n) ? b32[i0 + j] : NUM_G;
        }
    } else {
        if (i0 + 3 < n) {
            int4 a = *reinterpret_cast<const int4*>(b32 + 2 * i0);     // elems i0, i0+1
            int4 c = *reinterpret_cast<const int4*>(b32 + 2 * i0 + 4); // elems i0+2, i0+3
            v[0] = a.x; v[1] = a.z; v[2] = c.x; v[3] = c.z;
        } else {
            #pragma unroll
            for (int j = 0; j < 4; ++j)
                v[j] = (i0 + j < n) ? b32[(long long)(i0 + j) << 1] : NUM_G;
        }
    }

    #pragma unroll
    for (int j = 0; j < 4; ++j) {
        int cur = v[j];
        for (int g = prev + 1; g <= cur; ++g)
            g_seg_off[g] = i0 + j;
        prev = cur;
    }
}

__device__ __forceinline__ void acc(float4& s, float4& q, const float4 v)
{
    s.x += v.x; s.y += v.y; s.z += v.z; s.w += v.w;
    q.x += v.x * v.x; q.y += v.y * v.y;
    q.z += v.z * v.z; q.w += v.w * v.w;
}

__global__ __launch_bounds__(TPB, 2) void graphnorm_kernel(
    const float4* __restrict__ x4,
    const float*  __restrict__ weight,
    const float*  __restrict__ bias,
    float4*       __restrict__ out4)
{
    __shared__ float4 red_s[RG][D4];
    __shared__ float4 red_q[RG][D4];
    __shared__ float4 sc_s[D4];
    __shared__ float4 sh_s[D4];

    const int g   = blockIdx.x;
    const int tid = threadIdx.x;
    const int c4  = tid & (D4 - 1);   // float4 column
    const int rg  = tid >> 5;         // row group 0..15

    const int start = g_seg_off[g];
    const int end   = g_seg_off[g + 1];
    const int cnt   = end - start;

    // ---- Pass 1: per-column sum / sumsq (unroll x4: 4 independent
    //      LDG.128 per warp in flight) ----
    float4 s = make_float4(0.f, 0.f, 0.f, 0.f);
    float4 q = make_float4(0.f, 0.f, 0.f, 0.f);
    int r = start + rg;
    for (; r + 3 * RG < end; r += 4 * RG) {
        float4 v0 = x4[(r         ) * D4 + c4];
        float4 v1 = x4[(r +     RG) * D4 + c4];
        float4 v2 = x4[(r + 2 * RG) * D4 + c4];
        float4 v3 = x4[(r + 3 * RG) * D4 + c4];
        acc(s, q, v0);
        acc(s, q, v1);
        acc(s, q, v2);
        acc(s, q, v3);
    }
    for (; r < end; r += RG) {
        float4 v = x4[r * D4 + c4];
        acc(s, q, v);
    }
    red_s[rg][c4] = s;
    red_q[rg][c4] = q;
    __syncthreads();

    // ---- Flat parallel reduction + fold into scale/shift.
    //      128 threads, one scalar column each: 16 conflict-free LDS per
    //      sum, fully pipelined. 2 barriers total. ----
    if (tid < DHID) {
        const float* ps = reinterpret_cast<const float*>(red_s);
        const float* pq = reinterpret_cast<const float*>(red_q);
        float S = 0.f, Q = 0.f;
        #pragma unroll
        for (int k = 0; k < RG; ++k) {
            S += ps[k * DHID + tid];
            Q += pq[k * DHID + tid];
        }
        float w = weight[tid];
        float b = bias[tid];
        float sc, sh;
        if (cnt > 1) {
            float inv_n = 1.0f / (float)cnt;
            float m = S * inv_n;
            float v = Q * inv_n - m * m;
            sc = w * rsqrtf(v + EPSV);
            sh = b - m * sc;
        } else {
            // cnt <= 1: reference leaves mean=0, var=1
            sc = w * rsqrtf(1.0f + EPSV);
            sh = b;
        }
        reinterpret_cast<float*>(sc_s)[tid] = sc;
        reinterpret_cast<float*>(sh_s)[tid] = sh;
    }
    __syncthreads();

    // ---- Pass 2: normalize (unroll x2, hoisted sc/sh). x re-read hits L2;
    //      streaming stores keep the output from evicting x segments. ----
    const float4 sc = sc_s[c4];
    const float4 sh = sh_s[c4];
    const int jend = end * D4;
    int j = start * D4 + tid;
    for (; j + TPB < jend; j += 2 * TPB) {
        float4 v0 = x4[j];
        float4 v1 = x4[j + TPB];
        float4 o0, o1;
        o0.x = v0.x * sc.x + sh.x; o0.y = v0.y * sc.y + sh.y;
        o0.z = v0.z * sc.z + sh.z; o0.w = v0.w * sc.w + sh.w;
        o1.x = v1.x * sc.x + sh.x; o1.y = v1.y * sc.y + sh.y;
        o1.z = v1.z * sc.z + sh.z; o1.w = v1.w * sc.w + sh.w;
        __stcs(&out4[j      ], o0);
        __stcs(&out4[j + TPB], o1);
    }
    if (j < jend) {
        float4 v = x4[j];
        float4 o;
        o.x = v.x * sc.x + sh.x;
        o.y = v.y * sc.y + sh.y;
        o.z = v.z * sc.z + sh.z;
        o.w = v.w * sc.w + sh.w;
        __stcs(&out4[j], o);
    }
}

extern "C" void kernel_launch(void* const* d_in, const int* in_sizes, int n_in,
                              void* d_out, int out_size)
{
    const float* x      = (const float*)d_in[0];
    const int*   batch  = (const int*)d_in[1];   // int32 or int64; detected on device
    const float* weight = (const float*)d_in[2];
    const float* bias   = (const float*)d_in[3];
    float*       out    = (float*)d_out;

    int n = in_sizes[1];  // number of nodes

    int nthreads = n / 4 + 1;                   // one thread per 4 boundary slots
    offsets_kernel<<<(nthreads + 255) / 256, 256>>>(batch, n);
    graphnorm_kernel<<<NUM_G, TPB>>>(
        reinterpret_cast<const float4*>(x), weight, bias,
        reinterpret_cast<float4*>(out));
}

// round 13
// speedup vs baseline: 1.0808x; 1.0073x over previous
#include <cuda_runtime.h>

#define NUM_G 4096
#define D4    32          // 128 floats = 32 float4 per row
#define DHID  128
#define TPB   512
#define RG    16          // row groups in pass 1 (TPB / 32)
#define EPSV  1e-5f

__device__ int g_seg_off[NUM_G + 1];

// Vectorized scan-based offsets: each thread owns 4 consecutive positions
// i0..i0+3 of the virtual sequence val(-1)=-1, val(i)=batch[i] (i<n),
// val(n)=NUM_G, and writes g_seg_off[g]=i for every boundary it owns.
// Runtime dtype detection: if batch is int64 (LE), odd 32-bit words near the
// end are high words of values < 4096 -> all zero. If int32, tail ~4095.
__global__ void offsets_kernel(const int* __restrict__ b32, int n)
{
    // PDL: allow the dependent graphnorm grid to begin launching now.
    // Memory visibility of g_seg_off is still guaranteed by the consumer's
    // cudaGridDependencySynchronize(), which waits for THIS grid to complete.
    cudaTriggerProgrammaticLaunchCompletion();

    int t  = blockIdx.x * blockDim.x + threadIdx.x;
    int i0 = t * 4;
    if (i0 > n) return;
    int probe = b32[n - 1] | b32[n - 3] | b32[n - 5] | b32[n - 7];
    int sh = (probe == 0) ? 1 : 0;   // 1 => int64, element i at word (i << 1)

    int prev = (i0 > 0) ? b32[(long long)(i0 - 1) << sh] : -1;

    int v[4];
    if (sh == 0) {
        if (i0 + 3 < n) {
            int4 a = *reinterpret_cast<const int4*>(b32 + i0);   // 16B aligned
            v[0] = a.x; v[1] = a.y; v[2] = a.z; v[3] = a.w;
        } else {
            #pragma unroll
            for (int j = 0; j < 4; ++j)
                v[j] = (i0 + j < n) ? b32[i0 + j] : NUM_G;
        }
    } else {
        if (i0 + 3 < n) {
            int4 a = *reinterpret_cast<const int4*>(b32 + 2 * i0);     // elems i0, i0+1
            int4 c = *reinterpret_cast<const int4*>(b32 + 2 * i0 + 4); // elems i0+2, i0+3
            v[0] = a.x; v[1] = a.z; v[2] = c.x; v[3] = c.z;
        } else {
            #pragma unroll
            for (int j = 0; j < 4; ++j)
                v[j] = (i0 + j < n) ? b32[(long long)(i0 + j) << 1] : NUM_G;
        }
    }

    #pragma unroll
    for (int j = 0; j < 4; ++j) {
        int cur = v[j];
        for (int g = prev + 1; g <= cur; ++g)
            g_seg_off[g] = i0 + j;
        prev = cur;
    }
}

__device__ __forceinline__ void acc(float4& s, float4& q, const float4 v)
{
    s.x += v.x; s.y += v.y; s.z += v.z; s.w += v.w;
    q.x += v.x * v.x; q.y += v.y * v.y;
    q.z += v.z * v.z; q.w += v.w * v.w;
}

__global__ __launch_bounds__(TPB, 2) void graphnorm_kernel(
    const float4* __restrict__ x4,
    const float*  __restrict__ weight,
    const float*  __restrict__ bias,
    float4*       __restrict__ out4)
{
    __shared__ float4 red_s[RG][D4];
    __shared__ float4 red_q[RG][D4];
    __shared__ float4 sc_s[D4];
    __shared__ float4 sh_s[D4];

    const int g   = blockIdx.x;
    const int tid = threadIdx.x;
    const int c4  = tid & (D4 - 1);   // float4 column
    const int rg  = tid >> 5;         // row group 0..15

    // PDL: this grid was allowed to launch while offsets_kernel still runs.
    // Block here until offsets_kernel has completed and its writes to
    // g_seg_off are visible.
    cudaGridDependencySynchronize();

    const int start = g_seg_off[g];
    const int end   = g_seg_off[g + 1];
    const int cnt   = end - start;

    // ---- Pass 1: per-column sum / sumsq (unroll x4: 4 independent
    //      LDG.128 per warp in flight) ----
    float4 s = make_float4(0.f, 0.f, 0.f, 0.f);
    float4 q = make_float4(0.f, 0.f, 0.f, 0.f);
    int r = start + rg;
    for (; r + 3 * RG < end; r += 4 * RG) {
        float4 v0 = x4[(r         ) * D4 + c4];
        float4 v1 = x4[(r +     RG) * D4 + c4];
        float4 v2 = x4[(r + 2 * RG) * D4 + c4];
        float4 v3 = x4[(r + 3 * RG) * D4 + c4];
        acc(s, q, v0);
        acc(s, q, v1);
        acc(s, q, v2);
        acc(s, q, v3);
    }
    for (; r < end; r += RG) {
        float4 v = x4[r * D4 + c4];
        acc(s, q, v);
    }
    red_s[rg][c4] = s;
    red_q[rg][c4] = q;
    __syncthreads();

    // ---- Flat parallel reduction + fold into scale/shift.
    //      128 threads, one scalar column each: 16 conflict-free LDS per
    //      sum, fully pipelined. 2 barriers total. ----
    if (tid < DHID) {
        const float* ps = reinterpret_cast<const float*>(red_s);
        const float* pq = reinterpret_cast<const float*>(red_q);
        float S = 0.f, Q = 0.f;
        #pragma unroll
        for (int k = 0; k < RG; ++k) {
            S += ps[k * DHID + tid];
            Q += pq[k * DHID + tid];
        }
        float w = weight[tid];
        float b = bias[tid];
        float sc, sh;
        if (cnt > 1) {
            float inv_n = 1.0f / (float)cnt;
            float m = S * inv_n;
            float v = Q * inv_n - m * m;
            sc = w * rsqrtf(v + EPSV);
            sh = b - m * sc;
        } else {
            // cnt <= 1: reference leaves mean=0, var=1
            sc = w * rsqrtf(1.0f + EPSV);
            sh = b;
        }
        reinterpret_cast<float*>(sc_s)[tid] = sc;
        reinterpret_cast<float*>(sh_s)[tid] = sh;
    }
    __syncthreads();

    // ---- Pass 2: normalize (unroll x2, hoisted sc/sh). x re-read hits L2;
    //      streaming stores keep the output from evicting x segments. ----
    const float4 sc = sc_s[c4];
    const float4 sh = sh_s[c4];
    const int jend = end * D4;
    int j = start * D4 + tid;
    for (; j + TPB < jend; j += 2 * TPB) {
        float4 v0 = x4[j];
        float4 v1 = x4[j + TPB];
        float4 o0, o1;
        o0.x = v0.x * sc.x + sh.x; o0.y = v0.y * sc.y + sh.y;
        o0.z = v0.z * sc.z + sh.z; o0.w = v0.w * sc.w + sh.w;
        o1.x = v1.x * sc.x + sh.x; o1.y = v1.y * sc.y + sh.y;
        o1.z = v1.z * sc.z + sh.z; o1.w = v1.w * sc.w + sh.w;
        __stcs(&out4[j      ], o0);
        __stcs(&out4[j + TPB], o1);
    }
    if (j < jend) {
        float4 v = x4[j];
        float4 o;
        o.x = v.x * sc.x + sh.x;
        o.y = v.y * sc.y + sh.y;
        o.z = v.z * sc.z + sh.z;
        o.w = v.w * sc.w + sh.w;
        __stcs(&out4[j], o);
    }
}

extern "C" void kernel_launch(void* const* d_in, const int* in_sizes, int n_in,
                              void* d_out, int out_size)
{
    const float* x      = (const float*)d_in[0];
    const int*   batch  = (const int*)d_in[1];   // int32 or int64; detected on device
    const float* weight = (const float*)d_in[2];
    const float* bias   = (const float*)d_in[3];
    float*       out    = (float*)d_out;

    int n = in_sizes[1];  // number of nodes

    int nthreads = n / 4 + 1;                   // one thread per 4 boundary slots
    offsets_kernel<<<(nthreads + 255) / 256, 256>>>(batch, n);

    // Launch graphnorm with Programmatic Dependent Launch so it can begin
    // (and run its prologue) while offsets_kernel drains.
    cudaLaunchConfig_t cfg = {};
    cfg.gridDim  = dim3(NUM_G);
    cfg.blockDim = dim3(TPB);
    cfg.dynamicSmemBytes = 0;
    cfg.stream = 0;
    cudaLaunchAttribute attrs[1];
    attrs[0].id = cudaLaunchAttributeProgrammaticStreamSerialization;
    attrs[0].val.programmaticStreamSerializationAllowed = 1;
    cfg.attrs = attrs;
    cfg.numAttrs = 1;
    cudaLaunchKernelEx(&cfg, graphnorm_kernel,
                       reinterpret_cast<const float4*>(x), weight, bias,
                       reinterpret_cast<float4*>(out));
}